// round 1
// baseline (speedup 1.0000x reference)
#include <cuda_runtime.h>
#include <math.h>

#define NN 50000
#define EE 100000
// H = 32, ED = 1024, K_RWSE = 16

// ---------------- scratch (device globals; no allocations allowed) ----------------
__device__ float g_W[(size_t)EE * 1024];   // edge-conditioned weights (E,32,32) ~410MB
__device__ float g_gate[EE];
__device__ float g_deg[NN];
__device__ float g_degc[NN];
__device__ float g_rwse[NN * 16];
__device__ float g_tmp[NN];
__device__ float g_nf[NN * 32];            // init features (n_feat || rwse)
__device__ float g_outA[NN * 32];
__device__ float g_outB[NN * 32];
__device__ float g_neigh[NN * 32];

// ---------------- small utility kernels ----------------
__global__ void k_zero(float* p, int n) {
    int i = blockIdx.x * blockDim.x + threadIdx.x;
    if (i < n) p[i] = 0.f;
}

__global__ void k_deg(const int* __restrict__ dst) {
    int e = blockIdx.x * blockDim.x + threadIdx.x;
    if (e < EE) atomicAdd(&g_deg[dst[e]], 1.0f);
}

__global__ void k_degc() {
    int i = blockIdx.x * blockDim.x + threadIdx.x;
    if (i < NN) {
        float d = g_deg[i];
        float dc = (d == 0.f) ? 1.f : d;
        g_degc[i] = dc;
        g_rwse[i * 16] = dc;   // col 0 of RWSE
    }
}

__global__ void k_rwse_scatter(const int* __restrict__ src, const int* __restrict__ dst, int k) {
    int e = blockIdx.x * blockDim.x + threadIdx.x;
    if (e < EE) atomicAdd(&g_tmp[dst[e]], g_rwse[src[e] * 16 + (k - 1)]);
}

__global__ void k_rwse_norm(int k) {
    int i = blockIdx.x * blockDim.x + threadIdx.x;
    if (i < NN) g_rwse[i * 16 + k] = g_tmp[i] / g_degc[i];
}

// ---------------- gate: sigmoid(e_feat @ gate_w + gate_b), one warp per edge ----------------
__global__ void k_gate(const float* __restrict__ ef, const float* __restrict__ gw,
                       const float* __restrict__ gb) {
    int t = blockIdx.x * blockDim.x + threadIdx.x;
    int e = t >> 5;
    int lane = t & 31;
    if (e >= EE) return;
    const float* row = ef + (size_t)e * 1024;
    float s = 0.f;
#pragma unroll
    for (int j = 0; j < 32; j++)
        s += row[j * 32 + lane] * gw[j * 32 + lane];
#pragma unroll
    for (int off = 16; off > 0; off >>= 1)
        s += __shfl_down_sync(0xffffffffu, s, off);
    if (lane == 0) {
        float x = s + gb[0];
        g_gate[e] = 1.f / (1.f + expf(-x));
    }
}

// ---------------- big GEMM: W = relu(e_feat @ edge_proj_w + b) * gate ----------------
// A: (M,1024) row-major, B: (1024,1024) row-major, C -> g_W.
// classic 128x128x8 tile, 256 threads, 8x8 per thread, float4 loads.
__global__ void __launch_bounds__(256) k_gemm(const float* __restrict__ A,
                                              const float* __restrict__ B,
                                              const float* __restrict__ bias,
                                              int M) {
    const int K = 1024, NCOL = 1024;
    __shared__ float As[8][128];
    __shared__ float Bs[8][128];

    int row0 = blockIdx.y * 128;
    int col0 = blockIdx.x * 128;
    int t = threadIdx.x;

    int aRow  = t >> 1;           // 0..127
    int aCol4 = (t & 1) * 4;      // 0 or 4
    int bRow  = t >> 5;           // 0..7
    int bCol4 = (t & 31) * 4;     // 0..124

    int tr = (t >> 4) * 8;        // 0..120
    int tc = (t & 15) * 8;        // 0..120

    float acc[8][8];
#pragma unroll
    for (int i = 0; i < 8; i++)
#pragma unroll
        for (int j = 0; j < 8; j++) acc[i][j] = 0.f;

    bool aValid = (row0 + aRow) < M;
    const float* Aptr = A + (size_t)(row0 + aRow) * K + aCol4;
    const float* Bptr = B + (size_t)bRow * NCOL + col0 + bCol4;

    for (int k0 = 0; k0 < K; k0 += 8) {
        float4 av = make_float4(0.f, 0.f, 0.f, 0.f);
        if (aValid) av = *(const float4*)(Aptr + k0);
        As[aCol4 + 0][aRow] = av.x;
        As[aCol4 + 1][aRow] = av.y;
        As[aCol4 + 2][aRow] = av.z;
        As[aCol4 + 3][aRow] = av.w;

        float4 bv = *(const float4*)(Bptr + (size_t)k0 * NCOL);
        *(float4*)&Bs[bRow][bCol4] = bv;

        __syncthreads();
#pragma unroll
        for (int kk = 0; kk < 8; kk++) {
            float ra[8], rb[8];
            *(float4*)&ra[0] = *(const float4*)&As[kk][tr];
            *(float4*)&ra[4] = *(const float4*)&As[kk][tr + 4];
            *(float4*)&rb[0] = *(const float4*)&Bs[kk][tc];
            *(float4*)&rb[4] = *(const float4*)&Bs[kk][tc + 4];
#pragma unroll
            for (int i = 0; i < 8; i++)
#pragma unroll
                for (int j = 0; j < 8; j++) acc[i][j] += ra[i] * rb[j];
        }
        __syncthreads();
    }

#pragma unroll
    for (int i = 0; i < 8; i++) {
        int r = row0 + tr + i;
        if (r >= M) break;
        float g = g_gate[r];
        float* crow = g_W + (size_t)r * 1024 + col0 + tc;
#pragma unroll
        for (int j = 0; j < 8; j += 4) {
            float4 o;
            o.x = fmaxf(acc[i][j + 0] + bias[col0 + tc + j + 0], 0.f) * g;
            o.y = fmaxf(acc[i][j + 1] + bias[col0 + tc + j + 1], 0.f) * g;
            o.z = fmaxf(acc[i][j + 2] + bias[col0 + tc + j + 2], 0.f) * g;
            o.w = fmaxf(acc[i][j + 3] + bias[col0 + tc + j + 3], 0.f) * g;
            *(float4*)(crow + j) = o;
        }
    }
}

// ---------------- lin0: nf = [n_feat || rwse]; out = relu(nf @ lin0_w + b) ----------------
__global__ void k_lin0(const float* __restrict__ n_feat, const float* __restrict__ lw,
                       const float* __restrict__ lb) {
    __shared__ float s_w[1024];
    __shared__ float s_b[32];
    for (int i = threadIdx.x; i < 1024; i += blockDim.x) s_w[i] = lw[i];
    if (threadIdx.x < 32) s_b[threadIdx.x] = lb[threadIdx.x];
    __syncthreads();
    int i = blockIdx.x * blockDim.x + threadIdx.x;
    if (i >= NN) return;
    float nf[32];
#pragma unroll
    for (int h = 0; h < 16; h++) nf[h] = n_feat[i * 16 + h];
#pragma unroll
    for (int h = 0; h < 16; h++) nf[16 + h] = g_rwse[i * 16 + h];
#pragma unroll
    for (int h = 0; h < 32; h++) g_nf[i * 32 + h] = nf[h];
#pragma unroll
    for (int j = 0; j < 32; j++) {
        float a = s_b[j];
#pragma unroll
        for (int h = 0; h < 32; h++) a += nf[h] * s_w[h * 32 + j];
        g_outA[i * 32 + j] = fmaxf(a, 0.f);
    }
}

// ---------------- msg: msg_e = out[src_e] @ W_e, scatter-add into neigh. warp/edge ----------------
__global__ void k_msg(const int* __restrict__ src, const int* __restrict__ dst,
                      const float* __restrict__ cur) {
    int t = blockIdx.x * blockDim.x + threadIdx.x;
    int e = t >> 5;
    int lane = t & 31;
    if (e >= EE) return;
    int s = src[e];
    float v = cur[s * 32 + lane];
    const float* we = g_W + (size_t)e * 1024;
    float acc = 0.f;
#pragma unroll
    for (int h = 0; h < 32; h++)
        acc += __shfl_sync(0xffffffffu, v, h) * we[h * 32 + lane];
    atomicAdd(&g_neigh[dst[e] * 32 + lane], acc);
}

// ---------------- node update: m = relu(neigh/deg + out + cb); out' = [m||out]@Mw + mb ----------------
__global__ void k_node(const float* __restrict__ mw, const float* __restrict__ mb,
                       const float* __restrict__ cb, const float* __restrict__ cur,
                       float* __restrict__ nxt) {
    __shared__ float s_w[2048];
    __shared__ float s_b[32], s_cb[32];
    for (int i = threadIdx.x; i < 2048; i += blockDim.x) s_w[i] = mw[i];
    if (threadIdx.x < 32) { s_b[threadIdx.x] = mb[threadIdx.x]; s_cb[threadIdx.x] = cb[threadIdx.x]; }
    __syncthreads();
    int i = blockIdx.x * blockDim.x + threadIdx.x;
    if (i >= NN) return;
    float dc = g_degc[i];
    float o[32], m[32];
#pragma unroll
    for (int h = 0; h < 32; h++) o[h] = cur[i * 32 + h];
#pragma unroll
    for (int h = 0; h < 32; h++)
        m[h] = fmaxf(g_neigh[i * 32 + h] / dc + o[h] + s_cb[h], 0.f);
#pragma unroll
    for (int j = 0; j < 32; j++) {
        float a = s_b[j];
#pragma unroll
        for (int h = 0; h < 32; h++) a += m[h] * s_w[h * 32 + j];
#pragma unroll
        for (int h = 0; h < 32; h++) a += o[h] * s_w[(32 + h) * 32 + j];
        nxt[i * 32 + j] = a;
    }
}

// ---------------- group pooling scatter ----------------
__global__ void k_group(const int* __restrict__ src, const int* __restrict__ dst,
                        const float* __restrict__ cur) {
    int t = blockIdx.x * blockDim.x + threadIdx.x;
    int e = t >> 5;
    int lane = t & 31;
    if (e >= EE) return;
    atomicAdd(&g_neigh[dst[e] * 32 + lane], cur[src[e] * 32 + lane]);
}

// ---------------- final: out = [out||group]@Sw + sb + nf ----------------
__global__ void k_final(const float* __restrict__ sw, const float* __restrict__ sb,
                        const float* __restrict__ cur, float* __restrict__ outp) {
    __shared__ float s_w[2048];
    __shared__ float s_b[32];
    for (int i = threadIdx.x; i < 2048; i += blockDim.x) s_w[i] = sw[i];
    if (threadIdx.x < 32) s_b[threadIdx.x] = sb[threadIdx.x];
    __syncthreads();
    int i = blockIdx.x * blockDim.x + threadIdx.x;
    if (i >= NN) return;
    float dc = g_degc[i];
    float o[32], g[32];
#pragma unroll
    for (int h = 0; h < 32; h++) o[h] = cur[i * 32 + h];
#pragma unroll
    for (int h = 0; h < 32; h++) g[h] = g_neigh[i * 32 + h] / dc;
#pragma unroll
    for (int j = 0; j < 32; j++) {
        float a = s_b[j];
#pragma unroll
        for (int h = 0; h < 32; h++) a += o[h] * s_w[h * 32 + j];
#pragma unroll
        for (int h = 0; h < 32; h++) a += g[h] * s_w[(32 + h) * 32 + j];
        outp[i * 32 + j] = a + g_nf[i * 32 + j];
    }
}

// ---------------- launch ----------------
extern "C" void kernel_launch(void* const* d_in, const int* in_sizes, int n_in,
                              void* d_out, int out_size) {
    const float* n_feat = (const float*)d_in[0];
    const float* e_feat = (const float*)d_in[1];
    const int*   src    = (const int*)d_in[2];
    const int*   dst    = (const int*)d_in[3];
    const float* epw    = (const float*)d_in[4];
    const float* epb    = (const float*)d_in[5];
    const float* gw     = (const float*)d_in[6];
    const float* gb     = (const float*)d_in[7];
    const float* lw     = (const float*)d_in[8];
    const float* lb     = (const float*)d_in[9];
    const float* cb     = (const float*)d_in[10];
    const float* mw     = (const float*)d_in[11];
    const float* mb     = (const float*)d_in[12];
    const float* sw     = (const float*)d_in[13];
    const float* sb     = (const float*)d_in[14];
    float* outp = (float*)d_out;

    float *pA, *pB, *pDeg, *pTmp, *pNeigh;
    cudaGetSymbolAddress((void**)&pA, g_outA);
    cudaGetSymbolAddress((void**)&pB, g_outB);
    cudaGetSymbolAddress((void**)&pDeg, g_deg);
    cudaGetSymbolAddress((void**)&pTmp, g_tmp);
    cudaGetSymbolAddress((void**)&pNeigh, g_neigh);

    const int T = 256;
    const int gN  = (NN + T - 1) / T;           // per-node
    const int gE  = (EE + T - 1) / T;           // per-edge
    const int gEW = (EE * 32 + T - 1) / T;      // warp-per-edge

    // degrees
    k_zero<<<gN, T>>>(pDeg, NN);
    k_deg<<<gE, T>>>(dst);
    k_degc<<<gN, T>>>();

    // RWSE cols 1..15
    for (int k = 1; k < 16; k++) {
        k_zero<<<gN, T>>>(pTmp, NN);
        k_rwse_scatter<<<gE, T>>>(src, dst, k);
        k_rwse_norm<<<gN, T>>>(k);
    }

    // gate then big GEMM producing W
    k_gate<<<gEW, T>>>(e_feat, gw, gb);
    {
        dim3 grid(1024 / 128, (EE + 127) / 128);
        k_gemm<<<grid, 256>>>(e_feat, epw, epb, EE);
    }

    // lin0 (also stores nf/init)
    k_lin0<<<gN, T>>>(n_feat, lw, lb);

    // 3 NNConv steps (ping-pong A->B->A->B)
    float* cur = pA;
    float* nxt = pB;
    for (int s = 0; s < 3; s++) {
        k_zero<<<(NN * 32 + T - 1) / T, T>>>(pNeigh, NN * 32);
        k_msg<<<gEW, T>>>(src, dst, cur);
        k_node<<<gN, T>>>(mw, mb, cb, cur, nxt);
        float* t2 = cur; cur = nxt; nxt = t2;
    }

    // group pooling + final projection + residual
    k_zero<<<(NN * 32 + T - 1) / T, T>>>(pNeigh, NN * 32);
    k_group<<<gEW, T>>>(src, dst, cur);
    k_final<<<gN, T>>>(sw, sb, cur, outp);
}

// round 2
// speedup vs baseline: 1.9333x; 1.9333x over previous
#include <cuda_runtime.h>
#include <math.h>
#include <stdint.h>

#define NN 50000
#define EE 100000
#define MPAD 100096   // EE padded to multiple of 128
// H = 32, ED = 1024, K_RWSE = 16

// ---------------- scratch (device globals; no allocations allowed) ----------------
__device__ float g_W[(size_t)EE * 1024];      // edge-conditioned weights ~410MB
__device__ float g_At[(size_t)1024 * MPAD];   // e_feat transposed (tf32-rounded) ~410MB
__device__ float g_Br[1024 * 1024];           // edge_proj_w tf32-rounded (4MB)
__device__ float g_gate[EE];
__device__ float g_deg[NN];
__device__ float g_degc[NN];
__device__ float g_rwse[NN * 16];
__device__ float g_nf[NN * 32];
__device__ float g_outA[NN * 32];
__device__ float g_outB[NN * 32];
__device__ float g_neigh[NN * 32];

// ---------------- helpers ----------------
__device__ __forceinline__ float to_tf32(float x) {
    float r;
    asm("cvt.rna.tf32.f32 %0, %1;" : "=f"(r) : "f"(x));
    return r;
}

__device__ __forceinline__ void cp_async16(float* dst, const float* src) {
    uint32_t d = (uint32_t)__cvta_generic_to_shared(dst);
    asm volatile("cp.async.cg.shared.global [%0], [%1], 16;" :: "r"(d), "l"(src));
}

__device__ __forceinline__ void mma_tf32(float* c, const float* a, const float* b) {
    const uint32_t* A = reinterpret_cast<const uint32_t*>(a);
    const uint32_t* B = reinterpret_cast<const uint32_t*>(b);
    asm volatile(
        "mma.sync.aligned.m16n8k8.row.col.f32.tf32.tf32.f32 "
        "{%0,%1,%2,%3}, {%4,%5,%6,%7}, {%8,%9}, {%0,%1,%2,%3};"
        : "+f"(c[0]), "+f"(c[1]), "+f"(c[2]), "+f"(c[3])
        : "r"(A[0]), "r"(A[1]), "r"(A[2]), "r"(A[3]), "r"(B[0]), "r"(B[1]));
}

// ---------------- small utility kernels ----------------
__global__ void k_zero(float* p, int n) {
    int i = blockIdx.x * blockDim.x + threadIdx.x;
    if (i < n) p[i] = 0.f;
}

__global__ void k_deg(const int* __restrict__ dst) {
    int e = blockIdx.x * blockDim.x + threadIdx.x;
    if (e < EE) atomicAdd(&g_deg[dst[e]], 1.0f);
}

__global__ void k_degc() {
    int i = blockIdx.x * blockDim.x + threadIdx.x;
    if (i < NN) {
        float d = g_deg[i];
        float dc = (d == 0.f) ? 1.f : d;
        g_degc[i] = dc;
        g_rwse[i * 16] = dc;
    }
}

__global__ void k_rwse_scatter(const int* __restrict__ src, const int* __restrict__ dst, int k) {
    int e = blockIdx.x * blockDim.x + threadIdx.x;
    if (e < EE) atomicAdd(&g_rwse[dst[e] * 16 + k], g_rwse[src[e] * 16 + (k - 1)]);
}

__global__ void k_rwse_norm(int k) {
    int i = blockIdx.x * blockDim.x + threadIdx.x;
    if (i < NN) g_rwse[i * 16 + k] /= g_degc[i];
}

// ---------------- transpose e_feat -> g_At (with tf32 rounding) ----------------
__global__ void k_transpose(const float* __restrict__ A) {
    __shared__ float tile[32][33];
    int k0 = blockIdx.x * 32, m0 = blockIdx.y * 32;
    int tx = threadIdx.x, ty = threadIdx.y;  // 32 x 8
#pragma unroll
    for (int i = 0; i < 32; i += 8) {
        int m = m0 + ty + i;
        float v = (m < EE) ? A[(size_t)m * 1024 + k0 + tx] : 0.f;
        tile[ty + i][tx] = to_tf32(v);
    }
    __syncthreads();
#pragma unroll
    for (int i = 0; i < 32; i += 8) {
        int k = k0 + ty + i;
        g_At[(size_t)k * MPAD + m0 + tx] = tile[tx][ty + i];
    }
}

__global__ void k_roundB(const float* __restrict__ B) {
    int i = blockIdx.x * blockDim.x + threadIdx.x;
    if (i < 1024 * 1024) g_Br[i] = to_tf32(B[i]);
}

// ---------------- gate: sigmoid(e_feat @ gate_w + gate_b), one warp per edge ----------------
__global__ void k_gate(const float* __restrict__ ef, const float* __restrict__ gw,
                       const float* __restrict__ gb) {
    int t = blockIdx.x * blockDim.x + threadIdx.x;
    int e = t >> 5;
    int lane = t & 31;
    if (e >= EE) return;
    const float* row = ef + (size_t)e * 1024;
    float s = 0.f;
#pragma unroll
    for (int j = 0; j < 32; j++)
        s += row[j * 32 + lane] * gw[j * 32 + lane];
#pragma unroll
    for (int off = 16; off > 0; off >>= 1)
        s += __shfl_down_sync(0xffffffffu, s, off);
    if (lane == 0) {
        float x = s + gb[0];
        g_gate[e] = 1.f / (1.f + expf(-x));
    }
}

// ---------------- tf32 tensor-core GEMM ----------------
// C(M=100000 pad 100096, N=1024) = At^T (k-major) @ Br, epilogue relu(x+bias)*gate -> g_W
// Block tile 128x256x32, 8 warps, warp tile 64x64 (4 m-tiles x 8 n-tiles of m16n8k8).
#define BM 128
#define BN 256
#define BK 32
#define SA 136          // As row stride (floats), 136 % 32 == 8 -> conflict-free frags
#define SB 264          // Bs row stride
#define BUFSZ (BK * SA + BK * SB)

__global__ void __launch_bounds__(256, 1) k_gemm_mma(const float* __restrict__ bias) {
    extern __shared__ float smem[];
    const int t = threadIdx.x;
    const int l = t & 31, w = t >> 5;
    const int wm = w & 1, wn = w >> 1;     // 2 warps M x 4 warps N
    const int g = l >> 2, t4 = l & 3;
    const int row0 = blockIdx.y * BM;
    const int col0 = blockIdx.x * BN;

    float acc[4][8][4];
#pragma unroll
    for (int mt = 0; mt < 4; mt++)
#pragma unroll
        for (int nt = 0; nt < 8; nt++)
#pragma unroll
            for (int r = 0; r < 4; r++) acc[mt][nt][r] = 0.f;

    // async chunk loader: A chunk 32x128 (1024 x 16B), B chunk 32x256 (2048 x 16B)
    auto load_chunk = [&](int kb, int buf) {
        float* As = smem + buf * BUFSZ;
        float* Bs = As + BK * SA;
#pragma unroll
        for (int o = 0; o < 4; o++) {
            int lin = t + o * 256;          // 0..1023
            int k = lin >> 5, mq = (lin & 31) << 2;
            cp_async16(As + k * SA + mq, g_At + (size_t)(kb + k) * MPAD + row0 + mq);
        }
#pragma unroll
        for (int o = 0; o < 8; o++) {
            int lin = t + o * 256;          // 0..2047
            int k = lin >> 6, nq = (lin & 63) << 2;
            cp_async16(Bs + k * SB + nq, g_Br + (size_t)(kb + k) * 1024 + col0 + nq);
        }
    };

    load_chunk(0, 0);
    asm volatile("cp.async.commit_group;");

    const int NCH = 1024 / BK;  // 32
    for (int c = 0; c < NCH; c++) {
        int buf = c & 1;
        if (c + 1 < NCH) {
            load_chunk((c + 1) * BK, buf ^ 1);
            asm volatile("cp.async.commit_group;");
            asm volatile("cp.async.wait_group 1;");
        } else {
            asm volatile("cp.async.wait_group 0;");
        }
        __syncthreads();

        const float* As = smem + buf * BUFSZ;
        const float* Bs = As + BK * SA;
#pragma unroll
        for (int ks = 0; ks < 4; ks++) {
            const int k0 = ks * 8;
            float a[4][4];
#pragma unroll
            for (int mt = 0; mt < 4; mt++) {
                const float* ap = As + (k0 + t4) * SA + wm * 64 + mt * 16 + g;
                a[mt][0] = ap[0];
                a[mt][1] = ap[8];
                a[mt][2] = ap[4 * SA];
                a[mt][3] = ap[4 * SA + 8];
            }
            float b[8][2];
#pragma unroll
            for (int nt = 0; nt < 8; nt++) {
                const float* bp = Bs + (k0 + t4) * SB + wn * 64 + nt * 8 + g;
                b[nt][0] = bp[0];
                b[nt][1] = bp[4 * SB];
            }
#pragma unroll
            for (int mt = 0; mt < 4; mt++)
#pragma unroll
                for (int nt = 0; nt < 8; nt++)
                    mma_tf32(acc[mt][nt], a[mt], b[nt]);
        }
        __syncthreads();
    }

    // epilogue: relu(acc + bias) * gate -> g_W
#pragma unroll
    for (int mt = 0; mt < 4; mt++) {
        int r0 = row0 + wm * 64 + mt * 16 + g;
        int r1 = r0 + 8;
        float ga0 = (r0 < EE) ? g_gate[r0] : 0.f;
        float ga1 = (r1 < EE) ? g_gate[r1] : 0.f;
#pragma unroll
        for (int nt = 0; nt < 8; nt++) {
            int cc = col0 + wn * 64 + nt * 8 + 2 * t4;
            float2 bb = *(const float2*)&bias[cc];
            if (r0 < EE) {
                float2 o;
                o.x = fmaxf(acc[mt][nt][0] + bb.x, 0.f) * ga0;
                o.y = fmaxf(acc[mt][nt][1] + bb.y, 0.f) * ga0;
                *(float2*)&g_W[(size_t)r0 * 1024 + cc] = o;
            }
            if (r1 < EE) {
                float2 o;
                o.x = fmaxf(acc[mt][nt][2] + bb.x, 0.f) * ga1;
                o.y = fmaxf(acc[mt][nt][3] + bb.y, 0.f) * ga1;
                *(float2*)&g_W[(size_t)r1 * 1024 + cc] = o;
            }
        }
    }
}

// ---------------- lin0 ----------------
__global__ void k_lin0(const float* __restrict__ n_feat, const float* __restrict__ lw,
                       const float* __restrict__ lb) {
    __shared__ float s_w[1024];
    __shared__ float s_b[32];
    for (int i = threadIdx.x; i < 1024; i += blockDim.x) s_w[i] = lw[i];
    if (threadIdx.x < 32) s_b[threadIdx.x] = lb[threadIdx.x];
    __syncthreads();
    int i = blockIdx.x * blockDim.x + threadIdx.x;
    if (i >= NN) return;
    float nf[32];
#pragma unroll
    for (int h = 0; h < 16; h++) nf[h] = n_feat[i * 16 + h];
#pragma unroll
    for (int h = 0; h < 16; h++) nf[16 + h] = g_rwse[i * 16 + h];
#pragma unroll
    for (int h = 0; h < 32; h++) g_nf[i * 32 + h] = nf[h];
#pragma unroll
    for (int j = 0; j < 32; j++) {
        float a = s_b[j];
#pragma unroll
        for (int h = 0; h < 32; h++) a += nf[h] * s_w[h * 32 + j];
        g_outA[i * 32 + j] = fmaxf(a, 0.f);
    }
}

// ---------------- msg: warp per edge ----------------
__global__ void k_msg(const int* __restrict__ src, const int* __restrict__ dst,
                      const float* __restrict__ cur) {
    int t = blockIdx.x * blockDim.x + threadIdx.x;
    int e = t >> 5;
    int lane = t & 31;
    if (e >= EE) return;
    int s = src[e];
    float v = cur[s * 32 + lane];
    const float* we = g_W + (size_t)e * 1024;
    float acc = 0.f;
#pragma unroll
    for (int h = 0; h < 32; h++)
        acc += __shfl_sync(0xffffffffu, v, h) * we[h * 32 + lane];
    atomicAdd(&g_neigh[dst[e] * 32 + lane], acc);
}

// ---------------- node update ----------------
__global__ void k_node(const float* __restrict__ mw, const float* __restrict__ mb,
                       const float* __restrict__ cb, const float* __restrict__ cur,
                       float* __restrict__ nxt) {
    __shared__ float s_w[2048];
    __shared__ float s_b[32], s_cb[32];
    for (int i = threadIdx.x; i < 2048; i += blockDim.x) s_w[i] = mw[i];
    if (threadIdx.x < 32) { s_b[threadIdx.x] = mb[threadIdx.x]; s_cb[threadIdx.x] = cb[threadIdx.x]; }
    __syncthreads();
    int i = blockIdx.x * blockDim.x + threadIdx.x;
    if (i >= NN) return;
    float dc = g_degc[i];
    float o[32], m[32];
#pragma unroll
    for (int h = 0; h < 32; h++) o[h] = cur[i * 32 + h];
#pragma unroll
    for (int h = 0; h < 32; h++)
        m[h] = fmaxf(g_neigh[i * 32 + h] / dc + o[h] + s_cb[h], 0.f);
#pragma unroll
    for (int j = 0; j < 32; j++) {
        float a = s_b[j];
#pragma unroll
        for (int h = 0; h < 32; h++) a += m[h] * s_w[h * 32 + j];
#pragma unroll
        for (int h = 0; h < 32; h++) a += o[h] * s_w[(32 + h) * 32 + j];
        nxt[i * 32 + j] = a;
    }
}

// ---------------- group pooling ----------------
__global__ void k_group(const int* __restrict__ src, const int* __restrict__ dst,
                        const float* __restrict__ cur) {
    int t = blockIdx.x * blockDim.x + threadIdx.x;
    int e = t >> 5;
    int lane = t & 31;
    if (e >= EE) return;
    atomicAdd(&g_neigh[dst[e] * 32 + lane], cur[src[e] * 32 + lane]);
}

// ---------------- final ----------------
__global__ void k_final(const float* __restrict__ sw, const float* __restrict__ sb,
                        const float* __restrict__ cur, float* __restrict__ outp) {
    __shared__ float s_w[2048];
    __shared__ float s_b[32];
    for (int i = threadIdx.x; i < 2048; i += blockDim.x) s_w[i] = sw[i];
    if (threadIdx.x < 32) s_b[threadIdx.x] = sb[threadIdx.x];
    __syncthreads();
    int i = blockIdx.x * blockDim.x + threadIdx.x;
    if (i >= NN) return;
    float dc = g_degc[i];
    float o[32], g[32];
#pragma unroll
    for (int h = 0; h < 32; h++) o[h] = cur[i * 32 + h];
#pragma unroll
    for (int h = 0; h < 32; h++) g[h] = g_neigh[i * 32 + h] / dc;
#pragma unroll
    for (int j = 0; j < 32; j++) {
        float a = s_b[j];
#pragma unroll
        for (int h = 0; h < 32; h++) a += o[h] * s_w[h * 32 + j];
#pragma unroll
        for (int h = 0; h < 32; h++) a += g[h] * s_w[(32 + h) * 32 + j];
        outp[i * 32 + j] = a + g_nf[i * 32 + j];
    }
}

// ---------------- launch ----------------
extern "C" void kernel_launch(void* const* d_in, const int* in_sizes, int n_in,
                              void* d_out, int out_size) {
    const float* n_feat = (const float*)d_in[0];
    const float* e_feat = (const float*)d_in[1];
    const int*   src    = (const int*)d_in[2];
    const int*   dst    = (const int*)d_in[3];
    const float* epw    = (const float*)d_in[4];
    const float* epb    = (const float*)d_in[5];
    const float* gw     = (const float*)d_in[6];
    const float* gb     = (const float*)d_in[7];
    const float* lw     = (const float*)d_in[8];
    const float* lb     = (const float*)d_in[9];
    const float* cb     = (const float*)d_in[10];
    const float* mw     = (const float*)d_in[11];
    const float* mb     = (const float*)d_in[12];
    const float* sw     = (const float*)d_in[13];
    const float* sb     = (const float*)d_in[14];
    float* outp = (float*)d_out;

    float *pA, *pB, *pDeg, *pNeigh, *pRwse;
    cudaGetSymbolAddress((void**)&pA, g_outA);
    cudaGetSymbolAddress((void**)&pB, g_outB);
    cudaGetSymbolAddress((void**)&pDeg, g_deg);
    cudaGetSymbolAddress((void**)&pNeigh, g_neigh);
    cudaGetSymbolAddress((void**)&pRwse, g_rwse);

    static int smem_set = 0;
    if (!smem_set) {
        cudaFuncSetAttribute(k_gemm_mma, cudaFuncAttributeMaxDynamicSharedMemorySize,
                             2 * BUFSZ * (int)sizeof(float));
        smem_set = 1;
    }

    const int T = 256;
    const int gN  = (NN + T - 1) / T;
    const int gE  = (EE + T - 1) / T;
    const int gEW = (EE * 32 + T - 1) / T;

    // --- edge-conditioned weight pipeline (dominant) ---
    {
        dim3 tg(32, (MPAD + 31) / 32);
        k_transpose<<<tg, dim3(32, 8)>>>(e_feat);
    }
    k_roundB<<<(1024 * 1024 + T - 1) / T, T>>>(epw);
    k_gate<<<gEW, T>>>(e_feat, gw, gb);
    {
        dim3 grid(1024 / BN, MPAD / BM);
        k_gemm_mma<<<grid, 256, 2 * BUFSZ * (int)sizeof(float)>>>(epb);
    }

    // --- degrees + RWSE ---
    k_zero<<<gN, T>>>(pDeg, NN);
    k_zero<<<(NN * 16 + T - 1) / T, T>>>(pRwse, NN * 16);
    k_deg<<<gE, T>>>(dst);
    k_degc<<<gN, T>>>();
    for (int k = 1; k < 16; k++) {
        k_rwse_scatter<<<gE, T>>>(src, dst, k);
        k_rwse_norm<<<gN, T>>>(k);
    }

    // --- lin0 ---
    k_lin0<<<gN, T>>>(n_feat, lw, lb);

    // --- 3 NNConv steps ---
    float* cur = pA;
    float* nxt = pB;
    for (int s = 0; s < 3; s++) {
        k_zero<<<(NN * 32 + T - 1) / T, T>>>(pNeigh, NN * 32);
        k_msg<<<gEW, T>>>(src, dst, cur);
        k_node<<<gN, T>>>(mw, mb, cb, cur, nxt);
        float* t2 = cur; cur = nxt; nxt = t2;
    }

    // --- pooling + final ---
    k_zero<<<(NN * 32 + T - 1) / T, T>>>(pNeigh, NN * 32);
    k_group<<<gEW, T>>>(src, dst, cur);
    k_final<<<gN, T>>>(sw, sb, cur, outp);
}

// round 5
// speedup vs baseline: 4.0440x; 2.0918x over previous
#include <cuda_runtime.h>
#include <cuda_bf16.h>
#include <math.h>
#include <stdint.h>

#define NN 50000
#define EE 100000
#define MPAD 100096   // EE padded to multiple of 128
// H = 32, ED = 1024, K_RWSE = 16

typedef __nv_bfloat16 bf16;

// ---------------- scratch (device globals; no allocations allowed) ----------------
__device__ bf16  g_Wb[(size_t)EE * 1024];     // edge-conditioned weights, bf16 (~205MB)
__device__ bf16  g_Ab[(size_t)MPAD * 1024];   // e_feat in bf16, padded rows zero (~205MB)
__device__ bf16  g_Btb[1024 * 1024];          // edge_proj_w transposed [N][K], bf16 (2MB)
__device__ float g_gate[EE];
__device__ float g_deg[NN];
__device__ float g_degc[NN];
__device__ float g_rwse[NN * 16];
__device__ float g_nf[NN * 32];
__device__ float g_outA[NN * 32];
__device__ float g_outB[NN * 32];
__device__ float g_neigh[NN * 32];

// ---------------- helpers ----------------
__device__ __forceinline__ void cp_async16(void* dst, const void* src) {
    uint32_t d = (uint32_t)__cvta_generic_to_shared(dst);
    asm volatile("cp.async.cg.shared.global [%0], [%1], 16;" :: "r"(d), "l"(src));
}

__device__ __forceinline__ void mma_bf16(float* c, const uint32_t* a, const uint32_t* b) {
    asm volatile(
        "mma.sync.aligned.m16n8k16.row.col.f32.bf16.bf16.f32 "
        "{%0,%1,%2,%3}, {%4,%5,%6,%7}, {%8,%9}, {%0,%1,%2,%3};"
        : "+f"(c[0]), "+f"(c[1]), "+f"(c[2]), "+f"(c[3])
        : "r"(a[0]), "r"(a[1]), "r"(a[2]), "r"(a[3]), "r"(b[0]), "r"(b[1]));
}

// ---------------- small utility kernels ----------------
__global__ void k_zero(float* p, int n) {
    int i = blockIdx.x * blockDim.x + threadIdx.x;
    if (i < n) p[i] = 0.f;
}

__global__ void k_deg(const int* __restrict__ dst) {
    int e = blockIdx.x * blockDim.x + threadIdx.x;
    if (e < EE) atomicAdd(&g_deg[dst[e]], 1.0f);
}

__global__ void k_degc() {
    int i = blockIdx.x * blockDim.x + threadIdx.x;
    if (i < NN) {
        float d = g_deg[i];
        float dc = (d == 0.f) ? 1.f : d;
        g_degc[i] = dc;
        g_rwse[i * 16] = dc;   // col 0 of RWSE = degc
    }
}

// fused scatter: applies normalization of previous column on read
__global__ void k_rwse_scatter(const int* __restrict__ src, const int* __restrict__ dst, int k) {
    int e = blockIdx.x * blockDim.x + threadIdx.x;
    if (e >= EE) return;
    int s = src[e];
    float v = g_rwse[s * 16 + (k - 1)];
    if (k > 1) v /= g_degc[s];
    atomicAdd(&g_rwse[dst[e] * 16 + k], v);
}

// ---------------- convert e_feat -> bf16 (padded rows zeroed) ----------------
__global__ void k_convA(const float* __restrict__ A) {
    int i = blockIdx.x * blockDim.x + threadIdx.x;     // one 16B output per thread
    if (i >= MPAD * 128) return;
    int r = i >> 7;
    int c8 = (i & 127) << 3;
    bf16 o[8];
    if (r < EE) {
        float4 v0 = *(const float4*)(A + (size_t)r * 1024 + c8);
        float4 v1 = *(const float4*)(A + (size_t)r * 1024 + c8 + 4);
        o[0] = __float2bfloat16(v0.x); o[1] = __float2bfloat16(v0.y);
        o[2] = __float2bfloat16(v0.z); o[3] = __float2bfloat16(v0.w);
        o[4] = __float2bfloat16(v1.x); o[5] = __float2bfloat16(v1.y);
        o[6] = __float2bfloat16(v1.z); o[7] = __float2bfloat16(v1.w);
    } else {
#pragma unroll
        for (int j = 0; j < 8; j++) o[j] = __float2bfloat16(0.f);
    }
    *(uint4*)(g_Ab + (size_t)r * 1024 + c8) = *(uint4*)o;
}

// ---------------- transpose + convert edge_proj_w -> g_Btb [N][K] bf16 ----------------
__global__ void k_transB(const float* __restrict__ B) {
    __shared__ float t[32][33];
    int x0 = blockIdx.x * 32, y0 = blockIdx.y * 32;
    int tx = threadIdx.x, ty = threadIdx.y;  // 32 x 8
#pragma unroll
    for (int i = 0; i < 32; i += 8)
        t[ty + i][tx] = B[(size_t)(y0 + ty + i) * 1024 + x0 + tx];
    __syncthreads();
#pragma unroll
    for (int i = 0; i < 32; i += 8)
        g_Btb[(size_t)(x0 + ty + i) * 1024 + y0 + tx] = __float2bfloat16(t[tx][ty + i]);
}

// ---------------- gate: sigmoid(e_feat @ gate_w + gate_b), one warp per edge ----------------
__global__ void k_gate(const float* __restrict__ ef, const float* __restrict__ gw,
                       const float* __restrict__ gb) {
    int t = blockIdx.x * blockDim.x + threadIdx.x;
    int e = t >> 5;
    int lane = t & 31;
    if (e >= EE) return;
    const float* row = ef + (size_t)e * 1024;
    float s = 0.f;
#pragma unroll
    for (int j = 0; j < 32; j++)
        s += row[j * 32 + lane] * gw[j * 32 + lane];
#pragma unroll
    for (int off = 16; off > 0; off >>= 1)
        s += __shfl_down_sync(0xffffffffu, s, off);
    if (lane == 0) {
        float x = s + gb[0];
        g_gate[e] = 1.f / (1.f + expf(-x));
    }
}

// ---------------- bf16 tensor-core GEMM ----------------
// C(MPAD,1024) = g_Ab @ g_Btb^T ; epilogue relu(x+bias)*gate -> g_Wb (bf16)
// Block tile 128x256x64(halves). 8 warps, warp tile 64x64, m16n8k16 mma.
// Smem rows: stride 72 halves (36 words). 36 mod 32 = 4 -> frag LDS conflict-free.
#define BM 128
#define BN 256
#define BKH 64                       // K per chunk, in halves
#define SROW 72                      // smem row stride, halves
#define STAGE_HALVES ((BM + BN) * SROW)   // 27648 halves = 55296 B
#define SMEM_DYN (2 * STAGE_HALVES * 2)   // 110592 B

__global__ void __launch_bounds__(256, 1) k_gemm_bf16(const float* __restrict__ bias) {
    extern __shared__ bf16 smem[];
    const int t = threadIdx.x;
    const int l = t & 31, w = t >> 5;
    const int wm = w & 1, wn = w >> 1;     // 2 warps M x 4 warps N
    const int g = l >> 2, t4 = l & 3;
    const int row0 = blockIdx.y * BM;
    const int col0 = blockIdx.x * BN;

    float acc[4][8][4];
#pragma unroll
    for (int mt = 0; mt < 4; mt++)
#pragma unroll
        for (int nt = 0; nt < 8; nt++)
#pragma unroll
            for (int r = 0; r < 4; r++) acc[mt][nt][r] = 0.f;

    auto load_chunk = [&](int kb, int buf) {
        bf16* As = smem + buf * STAGE_HALVES;
        bf16* Bs = As + BM * SROW;
#pragma unroll
        for (int o = 0; o < 4; o++) {              // A: 128 rows x 128B
            int lin = t + o * 256;
            int m = lin >> 3, c = lin & 7;
            cp_async16(As + m * SROW + c * 8, g_Ab + (size_t)(row0 + m) * 1024 + kb + c * 8);
        }
#pragma unroll
        for (int o = 0; o < 8; o++) {              // B: 256 rows x 128B
            int lin = t + o * 256;
            int n = lin >> 3, c = lin & 7;
            cp_async16(Bs + n * SROW + c * 8, g_Btb + (size_t)(col0 + n) * 1024 + kb + c * 8);
        }
    };

    load_chunk(0, 0);
    asm volatile("cp.async.commit_group;");

    const int NCH = 1024 / BKH;  // 16
    for (int c = 0; c < NCH; c++) {
        int buf = c & 1;
        if (c + 1 < NCH) {
            load_chunk((c + 1) * BKH, buf ^ 1);
            asm volatile("cp.async.commit_group;");
            asm volatile("cp.async.wait_group 1;");
        } else {
            asm volatile("cp.async.wait_group 0;");
        }
        __syncthreads();

        const uint32_t* As32 = (const uint32_t*)(smem + buf * STAGE_HALVES);
        const uint32_t* Bs32 = As32 + BM * (SROW / 2);
#pragma unroll
        for (int ks = 0; ks < 4; ks++) {
            const int kw = ks * 8 + t4;            // word index in row
            uint32_t a[4][4];
#pragma unroll
            for (int mt = 0; mt < 4; mt++) {
                int rw = wm * 64 + mt * 16 + g;
                a[mt][0] = As32[rw * 36 + kw];
                a[mt][1] = As32[(rw + 8) * 36 + kw];
                a[mt][2] = As32[rw * 36 + kw + 4];
                a[mt][3] = As32[(rw + 8) * 36 + kw + 4];
            }
            uint32_t b[8][2];
#pragma unroll
            for (int nt = 0; nt < 8; nt++) {
                int nr = wn * 64 + nt * 8 + g;
                b[nt][0] = Bs32[nr * 36 + kw];
                b[nt][1] = Bs32[nr * 36 + kw + 4];
            }
#pragma unroll
            for (int mt = 0; mt < 4; mt++)
#pragma unroll
                for (int nt = 0; nt < 8; nt++)
                    mma_bf16(acc[mt][nt], a[mt], b[nt]);
        }
        __syncthreads();
    }

    // epilogue: relu(acc + bias) * gate -> g_Wb (bf16)
#pragma unroll
    for (int mt = 0; mt < 4; mt++) {
        int r0 = row0 + wm * 64 + mt * 16 + g;
        int r1 = r0 + 8;
        float ga0 = (r0 < EE) ? g_gate[r0] : 0.f;
        float ga1 = (r1 < EE) ? g_gate[r1] : 0.f;
#pragma unroll
        for (int nt = 0; nt < 8; nt++) {
            int cc = col0 + wn * 64 + nt * 8 + 2 * t4;
            float2 bb = *(const float2*)&bias[cc];
            if (r0 < EE) {
                __nv_bfloat162 h;
                h.x = __float2bfloat16(fmaxf(acc[mt][nt][0] + bb.x, 0.f) * ga0);
                h.y = __float2bfloat16(fmaxf(acc[mt][nt][1] + bb.y, 0.f) * ga0);
                *(__nv_bfloat162*)(g_Wb + (size_t)r0 * 1024 + cc) = h;
            }
            if (r1 < EE) {
                __nv_bfloat162 h;
                h.x = __float2bfloat16(fmaxf(acc[mt][nt][2] + bb.x, 0.f) * ga1);
                h.y = __float2bfloat16(fmaxf(acc[mt][nt][3] + bb.y, 0.f) * ga1);
                *(__nv_bfloat162*)(g_Wb + (size_t)r1 * 1024 + cc) = h;
            }
        }
    }
}

// ---------------- lin0 (applies RWSE normalization on read) ----------------
__global__ void k_lin0(const float* __restrict__ n_feat, const float* __restrict__ lw,
                       const float* __restrict__ lb) {
    __shared__ float s_w[1024];
    __shared__ float s_b[32];
    for (int i = threadIdx.x; i < 1024; i += blockDim.x) s_w[i] = lw[i];
    if (threadIdx.x < 32) s_b[threadIdx.x] = lb[threadIdx.x];
    __syncthreads();
    int i = blockIdx.x * blockDim.x + threadIdx.x;
    if (i >= NN) return;
    float dc = g_degc[i];
    float nf[32];
#pragma unroll
    for (int h = 0; h < 16; h++) nf[h] = n_feat[i * 16 + h];
    nf[16] = g_rwse[i * 16];
#pragma unroll
    for (int h = 1; h < 16; h++) nf[16 + h] = g_rwse[i * 16 + h] / dc;
#pragma unroll
    for (int h = 0; h < 32; h++) g_nf[i * 32 + h] = nf[h];
#pragma unroll
    for (int j = 0; j < 32; j++) {
        float a = s_b[j];
#pragma unroll
        for (int h = 0; h < 32; h++) a += nf[h] * s_w[h * 32 + j];
        g_outA[i * 32 + j] = fmaxf(a, 0.f);
    }
}

// ---------------- msg: warp per edge, W in bf16 ----------------
__global__ void k_msg(const int* __restrict__ src, const int* __restrict__ dst,
                      const float* __restrict__ cur) {
    int t = blockIdx.x * blockDim.x + threadIdx.x;
    int e = t >> 5;
    int lane = t & 31;
    if (e >= EE) return;
    int s = src[e];
    float v = cur[s * 32 + lane];
    const bf16* we = g_Wb + (size_t)e * 1024;
    float acc = 0.f;
#pragma unroll
    for (int h = 0; h < 32; h++)
        acc += __shfl_sync(0xffffffffu, v, h) * __bfloat162float(we[h * 32 + lane]);
    atomicAdd(&g_neigh[dst[e] * 32 + lane], acc);
}

// ---------------- node update ----------------
__global__ void k_node(const float* __restrict__ mw, const float* __restrict__ mb,
                       const float* __restrict__ cb, const float* __restrict__ cur,
                       float* __restrict__ nxt) {
    __shared__ float s_w[2048];
    __shared__ float s_b[32], s_cb[32];
    for (int i = threadIdx.x; i < 2048; i += blockDim.x) s_w[i] = mw[i];
    if (threadIdx.x < 32) { s_b[threadIdx.x] = mb[threadIdx.x]; s_cb[threadIdx.x] = cb[threadIdx.x]; }
    __syncthreads();
    int i = blockIdx.x * blockDim.x + threadIdx.x;
    if (i >= NN) return;
    float dc = g_degc[i];
    float o[32], m[32];
#pragma unroll
    for (int h = 0; h < 32; h++) o[h] = cur[i * 32 + h];
#pragma unroll
    for (int h = 0; h < 32; h++)
        m[h] = fmaxf(g_neigh[i * 32 + h] / dc + o[h] + s_cb[h], 0.f);
#pragma unroll
    for (int j = 0; j < 32; j++) {
        float a = s_b[j];
#pragma unroll
        for (int h = 0; h < 32; h++) a += m[h] * s_w[h * 32 + j];
#pragma unroll
        for (int h = 0; h < 32; h++) a += o[h] * s_w[(32 + h) * 32 + j];
        nxt[i * 32 + j] = a;
    }
}

// ---------------- group pooling ----------------
__global__ void k_group(const int* __restrict__ src, const int* __restrict__ dst,
                        const float* __restrict__ cur) {
    int t = blockIdx.x * blockDim.x + threadIdx.x;
    int e = t >> 5;
    int lane = t & 31;
    if (e >= EE) return;
    atomicAdd(&g_neigh[dst[e] * 32 + lane], cur[src[e] * 32 + lane]);
}

// ---------------- final ----------------
__global__ void k_final(const float* __restrict__ sw, const float* __restrict__ sb,
                        const float* __restrict__ cur, float* __restrict__ outp) {
    __shared__ float s_w[2048];
    __shared__ float s_b[32];
    for (int i = threadIdx.x; i < 2048; i += blockDim.x) s_w[i] = sw[i];
    if (threadIdx.x < 32) s_b[threadIdx.x] = sb[threadIdx.x];
    __syncthreads();
    int i = blockIdx.x * blockDim.x + threadIdx.x;
    if (i >= NN) return;
    float dc = g_degc[i];
    float o[32], g[32];
#pragma unroll
    for (int h = 0; h < 32; h++) o[h] = cur[i * 32 + h];
#pragma unroll
    for (int h = 0; h < 32; h++) g[h] = g_neigh[i * 32 + h] / dc;
#pragma unroll
    for (int j = 0; j < 32; j++) {
        float a = s_b[j];
#pragma unroll
        for (int h = 0; h < 32; h++) a += o[h] * s_w[h * 32 + j];
#pragma unroll
        for (int h = 0; h < 32; h++) a += g[h] * s_w[(32 + h) * 32 + j];
        outp[i * 32 + j] = a + g_nf[i * 32 + j];
    }
}

// ---------------- launch ----------------
extern "C" void kernel_launch(void* const* d_in, const int* in_sizes, int n_in,
                              void* d_out, int out_size) {
    const float* n_feat = (const float*)d_in[0];
    const float* e_feat = (const float*)d_in[1];
    const int*   src    = (const int*)d_in[2];
    const int*   dst    = (const int*)d_in[3];
    const float* epw    = (const float*)d_in[4];
    const float* epb    = (const float*)d_in[5];
    const float* gw     = (const float*)d_in[6];
    const float* gb     = (const float*)d_in[7];
    const float* lw     = (const float*)d_in[8];
    const float* lb     = (const float*)d_in[9];
    const float* cb     = (const float*)d_in[10];
    const float* mw     = (const float*)d_in[11];
    const float* mb     = (const float*)d_in[12];
    const float* sw     = (const float*)d_in[13];
    const float* sb     = (const float*)d_in[14];
    float* outp = (float*)d_out;

    float *pA, *pB, *pDeg, *pNeigh, *pRwse;
    cudaGetSymbolAddress((void**)&pA, g_outA);
    cudaGetSymbolAddress((void**)&pB, g_outB);
    cudaGetSymbolAddress((void**)&pDeg, g_deg);
    cudaGetSymbolAddress((void**)&pNeigh, g_neigh);
    cudaGetSymbolAddress((void**)&pRwse, g_rwse);

    static int attr_set = 0;
    if (!attr_set) {
        cudaFuncSetAttribute(k_gemm_bf16, cudaFuncAttributeMaxDynamicSharedMemorySize, SMEM_DYN);
        attr_set = 1;
    }

    const int T = 256;
    const int gN  = (NN + T - 1) / T;
    const int gE  = (EE + T - 1) / T;
    const int gEW = (EE * 32 + T - 1) / T;

    // --- edge-conditioned weight pipeline (dominant) ---
    k_transB<<<dim3(32, 32), dim3(32, 8)>>>(epw);
    k_convA<<<(MPAD * 128 + T - 1) / T, T>>>(e_feat);
    k_gate<<<gEW, T>>>(e_feat, gw, gb);
    {
        dim3 grid(1024 / BN, MPAD / BM);
        k_gemm_bf16<<<grid, 256, SMEM_DYN>>>(epb);
    }

    // --- degrees + RWSE ---
    k_zero<<<gN, T>>>(pDeg, NN);
    k_zero<<<(NN * 16 + T - 1) / T, T>>>(pRwse, NN * 16);
    k_deg<<<gE, T>>>(dst);
    k_degc<<<gN, T>>>();
    for (int k = 1; k < 16; k++)
        k_rwse_scatter<<<gE, T>>>(src, dst, k);

    // --- lin0 ---
    k_lin0<<<gN, T>>>(n_feat, lw, lb);

    // --- 3 NNConv steps ---
    float* cur = pA;
    float* nxt = pB;
    for (int s = 0; s < 3; s++) {
        k_zero<<<(NN * 32 + T - 1) / T, T>>>(pNeigh, NN * 32);
        k_msg<<<gEW, T>>>(src, dst, cur);
        k_node<<<gN, T>>>(mw, mb, cb, cur, nxt);
        float* t2 = cur; cur = nxt; nxt = t2;
    }

    // --- pooling + final ---
    k_zero<<<(NN * 32 + T - 1) / T, T>>>(pNeigh, NN * 32);
    k_group<<<gEW, T>>>(src, dst, cur);
    k_final<<<gN, T>>>(sw, sb, cur, outp);
}